// round 15
// baseline (speedup 1.0000x reference)
#include <cuda_runtime.h>
#include <cstdint>
#include <math.h>

#define EMBED 768
#define HEADS 12
#define HDIM  64
#define BATCH 2
#define SEQ   2048
#define MROWS (BATCH * SEQ)

// ---------------------------------------------------------------------------
// Scratch (allocation-free: __device__ globals)
// ---------------------------------------------------------------------------
__device__ float g_q[(size_t)BATCH * HEADS * SEQ * HDIM];   // [B,H,T,Dh] tf32, Q pre-scaled
__device__ float g_k[(size_t)BATCH * HEADS * SEQ * HDIM];
__device__ float g_v[(size_t)BATCH * HEADS * SEQ * HDIM];
__device__ float g_att[(size_t)BATCH * SEQ * EMBED];        // [B,T,E] tf32-rounded
// tf32 pre-rounded operands for cp.async staging
__device__ float g_aq[(size_t)MROWS * EMBED];
__device__ float g_ak[(size_t)MROWS * EMBED];
__device__ float g_av[(size_t)MROWS * EMBED];
__device__ float g_wq[(size_t)EMBED * EMBED];
__device__ float g_wk[(size_t)EMBED * EMBED];
__device__ float g_wv[(size_t)EMBED * EMBED];
__device__ float g_wo[(size_t)EMBED * EMBED];

__device__ __forceinline__ float to_tf32(float x) {
    float y; asm("cvt.rna.tf32.f32 %0, %1;" : "=f"(y) : "f"(x)); return y;
}
__device__ __forceinline__ uint32_t smem_u32(const void* p) {
    uint32_t a;
    asm("{ .reg .u64 t; cvta.to.shared.u64 t, %1; cvt.u32.u64 %0, t; }" : "=r"(a) : "l"(p));
    return a;
}

// m16n8k8 tf32 mma (hardware-verified R5/R10/R11/R13)
__device__ __forceinline__ void mma8(float (&c)[4],
                                     uint32_t a0, uint32_t a1, uint32_t a2, uint32_t a3,
                                     uint32_t b0, uint32_t b1) {
    asm volatile(
        "mma.sync.aligned.m16n8k8.row.col.f32.tf32.tf32.f32 "
        "{%0,%1,%2,%3}, {%4,%5,%6,%7}, {%8,%9}, {%0,%1,%2,%3};"
        : "+f"(c[0]), "+f"(c[1]), "+f"(c[2]), "+f"(c[3])
        : "r"(a0), "r"(a1), "r"(a2), "r"(a3), "r"(b0), "r"(b1));
}

#define F2U(x) __float_as_uint(x)

#define CP16(dst_u32, src_ptr) \
    asm volatile("cp.async.cg.shared.global [%0], [%1], 16;" \
                 :: "r"(dst_u32), "l"(__cvta_generic_to_global(src_ptr)) : "memory")
#define CP_COMMIT() asm volatile("cp.async.commit_group;" ::: "memory")
#define CP_WAIT0()  asm volatile("cp.async.wait_group 0;"  ::: "memory")

// ---------------------------------------------------------------------------
// One-time tf32 pre-round passes (idempotent -> math identical to R12/R13)
// ---------------------------------------------------------------------------
__global__ __launch_bounds__(256)
void round_in(const float* __restrict__ a, const float* __restrict__ b,
              const float* __restrict__ c, float* __restrict__ da,
              float* __restrict__ db, float* __restrict__ dc)
{
    const float* s = (blockIdx.z == 0) ? a : (blockIdx.z == 1) ? b : c;
    float*       d = (blockIdx.z == 0) ? da : (blockIdx.z == 1) ? db : dc;
    const size_t i = ((size_t)blockIdx.x * 256 + threadIdx.x) * 4;
    float4 v = *(const float4*)(s + i);
    v.x = to_tf32(v.x); v.y = to_tf32(v.y); v.z = to_tf32(v.z); v.w = to_tf32(v.w);
    *(float4*)(d + i) = v;
}
__global__ __launch_bounds__(256)
void round_w(const float* __restrict__ a, const float* __restrict__ b,
             const float* __restrict__ c, const float* __restrict__ e,
             float* __restrict__ da, float* __restrict__ db,
             float* __restrict__ dc, float* __restrict__ de)
{
    const float* s = (blockIdx.z == 0) ? a : (blockIdx.z == 1) ? b
                   : (blockIdx.z == 2) ? c : e;
    float*       d = (blockIdx.z == 0) ? da : (blockIdx.z == 1) ? db
                   : (blockIdx.z == 2) ? dc : de;
    const size_t i = ((size_t)blockIdx.x * 256 + threadIdx.x) * 4;
    float4 v = *(const float4*)(s + i);
    v.x = to_tf32(v.x); v.y = to_tf32(v.y); v.z = to_tf32(v.z); v.w = to_tf32(v.w);
    *(float4*)(d + i) = v;
}

// ---------------------------------------------------------------------------
// GEMM v3: R13 layout (CTA 128x128, 256 thr, 8 warps 4m x 2n, warp tile
// 32x64; verified fragment code) with cp.async double-buffered staging of
// pre-rounded operands. No LDG round trip, no cvt, no prefetch registers.
// smem: As[2][128][36], Bs[2][32][136].
// ---------------------------------------------------------------------------
#define GEMM_PREAMBLE                                          \
    extern __shared__ float sm[];                              \
    float* As = sm;                                            \
    float* Bs = sm + 2 * 128 * 36;                             \
    const int tid  = threadIdx.x;                              \
    const int lane = tid & 31;                                 \
    const int g    = lane >> 2;                                \
    const int t    = lane & 3;                                 \
    const int wid  = tid >> 5;                                 \
    const int wm   = wid >> 1;                                 \
    const int wn   = wid & 1;                                  \
    const int m0   = blockIdx.y * 128;                         \
    const int n0   = blockIdx.x * 128;                         \
    const int ra = tid >> 1, ha = tid & 1;                     \
    const int kb = tid >> 3, nq = tid & 7;

#define GEMM_MAINLOOP(A, W)                                                      \
    const uint32_t adst[2] = { smem_u32(As + ra * 36 + ha * 16),                 \
                               smem_u32(As + 128 * 36 + ra * 36 + ha * 16) };    \
    const uint32_t bdst[2] = { smem_u32(Bs + kb * 136 + nq * 16),                \
                               smem_u32(Bs + 32 * 136 + kb * 136 + nq * 16) };   \
    const float* asrc = (A) + (size_t)(m0 + ra) * EMBED + ha * 16;               \
    const float* bsrc = (W) + (size_t)kb * EMBED + n0 + nq * 16;                 \
    float c[2][8][4];                                                            \
    _Pragma("unroll")                                                            \
    for (int ma = 0; ma < 2; ++ma)                                               \
        _Pragma("unroll")                                                        \
        for (int j = 0; j < 8; ++j)                                              \
            _Pragma("unroll")                                                    \
            for (int q = 0; q < 4; ++q) c[ma][j][q] = 0.f;                       \
    _Pragma("unroll")                                                            \
    for (int i = 0; i < 4; ++i) {                                                \
        CP16(adst[0] + i * 16, asrc + 4 * i);                                    \
        CP16(bdst[0] + i * 16, bsrc + 4 * i);                                    \
    }                                                                            \
    CP_COMMIT();                                                                 \
    CP_WAIT0();                                                                  \
    __syncthreads();                                                             \
    for (int ch = 0; ch < 24; ++ch) {                                            \
        const int buf = ch & 1;                                                  \
        if (ch + 1 < 24) {                                                       \
            const float* an = asrc + (ch + 1) * 32;                              \
            const float* bn = bsrc + (size_t)(ch + 1) * 32 * EMBED;              \
            _Pragma("unroll")                                                    \
            for (int i = 0; i < 4; ++i) {                                        \
                CP16(adst[buf ^ 1] + i * 16, an + 4 * i);                        \
                CP16(bdst[buf ^ 1] + i * 16, bn + 4 * i);                        \
            }                                                                    \
            CP_COMMIT();                                                         \
        }                                                                        \
        const float* Ab = As + buf * 128 * 36;                                   \
        const float* Bb = Bs + buf * 32 * 136;                                   \
        _Pragma("unroll")                                                        \
        for (int s = 0; s < 4; ++s) {                                            \
            uint32_t a[2][4];                                                    \
            _Pragma("unroll")                                                    \
            for (int ma = 0; ma < 2; ++ma) {                                     \
                const int rb = wm * 32 + ma * 16;                                \
                a[ma][0] = F2U(Ab[(rb + g)     * 36 + 8 * s + t]);               \
                a[ma][1] = F2U(Ab[(rb + g + 8) * 36 + 8 * s + t]);               \
                a[ma][2] = F2U(Ab[(rb + g)     * 36 + 8 * s + t + 4]);           \
                a[ma][3] = F2U(Ab[(rb + g + 8) * 36 + 8 * s + t + 4]);           \
            }                                                                    \
            _Pragma("unroll")                                                    \
            for (int j = 0; j < 8; ++j) {                                        \
                const int col = wn * 64 + 8 * j + g;                             \
                const uint32_t b0 = F2U(Bb[(8 * s + t)     * 136 + col]);        \
                const uint32_t b1 = F2U(Bb[(8 * s + t + 4) * 136 + col]);        \
                mma8(c[0][j], a[0][0], a[0][1], a[0][2], a[0][3], b0, b1);       \
                mma8(c[1][j], a[1][0], a[1][1], a[1][2], a[1][3], b0, b1);       \
            }                                                                    \
        }                                                                        \
        if (ch + 1 < 24) { CP_WAIT0(); }                                         \
        __syncthreads();                                                         \
    }

// ---------------------------------------------------------------------------
// Fused QKV projection: z = 0/1/2 -> Q/K/V. Writes [B,H,T,Dh], tf32-rounded,
// Q pre-scaled by 0.125.
// ---------------------------------------------------------------------------
__global__ __launch_bounds__(256, 2)
void gemm_qkv(const float* __restrict__ bq, const float* __restrict__ bk,
              const float* __restrict__ bv,
              float* __restrict__ Cq, float* __restrict__ Ck, float* __restrict__ Cv)
{
    GEMM_PREAMBLE
    const int z = blockIdx.z;
    const float* A    = (z == 0) ? g_aq : (z == 1) ? g_ak : g_av;
    const float* W    = (z == 0) ? g_wq : (z == 1) ? g_wk : g_wv;
    const float* bias = (z == 0) ? bq : (z == 1) ? bk : bv;
    float*       C    = (z == 0) ? Cq : (z == 1) ? Ck : Cv;
    const float  scl  = (z == 0) ? 0.125f : 1.0f;

    GEMM_MAINLOOP(A, W)

#pragma unroll
    for (int ma = 0; ma < 2; ++ma) {
        const int r0 = m0 + wm * 32 + ma * 16 + g;
        const int r1 = r0 + 8;
#pragma unroll
        for (int j = 0; j < 8; ++j) {
            const int n = n0 + wn * 64 + 8 * j + 2 * t;
            const float bx = bias[n], by = bias[n + 1];
            float2 v0 = make_float2(to_tf32((c[ma][j][0] + bx) * scl),
                                    to_tf32((c[ma][j][1] + by) * scl));
            float2 v1 = make_float2(to_tf32((c[ma][j][2] + bx) * scl),
                                    to_tf32((c[ma][j][3] + by) * scl));
            const int h = n >> 6, d = n & 63;
            const int b0r = r0 >> 11, t0r = r0 & 2047;
            const int b1r = r1 >> 11, t1r = r1 & 2047;
            *(float2*)&C[(((size_t)b0r * HEADS + h) * SEQ + t0r) * HDIM + d] = v0;
            *(float2*)&C[(((size_t)b1r * HEADS + h) * SEQ + t1r) * HDIM + d] = v1;
        }
    }
}

// ---------------------------------------------------------------------------
// Output projection: fp32 [M, E]
// ---------------------------------------------------------------------------
__global__ __launch_bounds__(256, 2)
void gemm_out(const float* __restrict__ bias, float* __restrict__ C)
{
    GEMM_PREAMBLE
    GEMM_MAINLOOP(g_att, g_wo)

#pragma unroll
    for (int ma = 0; ma < 2; ++ma) {
        const int r0 = m0 + wm * 32 + ma * 16 + g;
        const int r1 = r0 + 8;
#pragma unroll
        for (int j = 0; j < 8; ++j) {
            const int n = n0 + wn * 64 + 8 * j + 2 * t;
            const float bx = bias[n], by = bias[n + 1];
            *(float2*)&C[(size_t)r0 * EMBED + n] = make_float2(c[ma][j][0] + bx, c[ma][j][1] + by);
            *(float2*)&C[(size_t)r1 * EMBED + n] = make_float2(c[ma][j][2] + bx, c[ma][j][3] + by);
        }
    }
}

// ---------------------------------------------------------------------------
// tf32 flash attention (R13-verified): 256 threads, 8 warps, 16 q-rows/warp,
// cp.async double-buffered 64-key chunks, P-in-registers.
// Epilogue now writes tf32-rounded values (feeds gemm_out's cp.async path).
// ---------------------------------------------------------------------------
__global__ __launch_bounds__(256, 2)
void attn_tc(const float* __restrict__ Q, const float* __restrict__ K,
             const float* __restrict__ V, float* __restrict__ out)
{
    extern __shared__ float sm[];
    float* Qs  = sm;                     // 128*68
    float* Ks0 = Qs + 128 * 68;
    float* Ks1 = Ks0 + 64 * 68;
    float* Vs0 = Ks1 + 64 * 68;
    float* Vs1 = Vs0 + 64 * 72;

    const int tid  = threadIdx.x;
    const int lane = tid & 31;
    const int g    = lane >> 2;
    const int t    = lane & 3;
    const int w    = tid >> 5;
    const int bh   = blockIdx.y;
    const int q0   = blockIdx.x * 128;

    const float* Qp = Q + (size_t)bh * SEQ * HDIM;
    const float* Kp = K + (size_t)bh * SEQ * HDIM;
    const float* Vp = V + (size_t)bh * SEQ * HDIM;

    const int kr = tid >> 2, sk = tid & 3;
    const uint32_t kdst[2] = { smem_u32(Ks0 + kr * 68 + sk * 16),
                               smem_u32(Ks1 + kr * 68 + sk * 16) };
    const uint32_t vdst[2] = { smem_u32(Vs0 + kr * 72 + sk * 16),
                               smem_u32(Vs1 + kr * 72 + sk * 16) };
    const float* kcur = Kp + (size_t)kr * HDIM + sk * 16;
    const float* vcur = Vp + (size_t)kr * HDIM + sk * 16;

    {
#pragma unroll
        for (int i = 0; i < 4; ++i) {
            CP16(kdst[0] + i * 16, kcur + 4 * i);
            CP16(vdst[0] + i * 16, vcur + 4 * i);
        }
        CP_COMMIT();
        const int rr = tid >> 1, sq = tid & 1;
        const float* qp = Qp + (size_t)(q0 + rr) * HDIM + sq * 32;
        float* qd = Qs + rr * 68 + sq * 32;
#pragma unroll
        for (int i = 0; i < 8; ++i)
            *(float4*)(qd + 4 * i) = *(const float4*)(qp + 4 * i);
    }
    CP_WAIT0();
    __syncthreads();

    float m0s = -INFINITY, m1s = -INFINITY, l0s = 0.f, l1s = 0.f;
    float o[8][4];
#pragma unroll
    for (int j = 0; j < 8; ++j)
#pragma unroll
        for (int q = 0; q < 4; ++q) o[j][q] = 0.f;

    const int srcA = 4 * g + (t >> 1);
    const int srcB = srcA + 2;
    const bool odd = (t & 1) != 0;

    for (int cch = 0; cch < 32; ++cch) {
        const int buf = cch & 1;
        if (cch + 1 < 32) {
            const size_t off = (size_t)(cch + 1) * 64 * HDIM;
            const float* kn = kcur + off;
            const float* vn = vcur + off;
#pragma unroll
            for (int i = 0; i < 4; ++i) {
                CP16(kdst[buf ^ 1] + i * 16, kn + 4 * i);
                CP16(vdst[buf ^ 1] + i * 16, vn + 4 * i);
            }
            CP_COMMIT();
        }

        const float* Ksb = buf ? Ks1 : Ks0;
        const float* Vsb = buf ? Vs1 : Vs0;

        float s[8][4];
#pragma unroll
        for (int j = 0; j < 8; ++j)
#pragma unroll
            for (int q = 0; q < 4; ++q) s[j][q] = 0.f;

#pragma unroll
        for (int ks = 0; ks < 8; ++ks) {
            const float* qr = Qs + (16 * w + g) * 68 + ks * 8;
            const uint32_t a0 = F2U(qr[t]);
            const uint32_t a1 = F2U(qr[8 * 68 + t]);
            const uint32_t a2 = F2U(qr[t + 4]);
            const uint32_t a3 = F2U(qr[8 * 68 + t + 4]);
#pragma unroll
            for (int j2 = 0; j2 < 8; ++j2) {
                const float* kp2 = Ksb + (8 * j2 + g) * 68 + ks * 8;
                mma8(s[j2], a0, a1, a2, a3, F2U(kp2[t]), F2U(kp2[t + 4]));
            }
        }

        float mx0 = -INFINITY, mx1 = -INFINITY;
#pragma unroll
        for (int j = 0; j < 8; ++j) {
            mx0 = fmaxf(mx0, fmaxf(s[j][0], s[j][1]));
            mx1 = fmaxf(mx1, fmaxf(s[j][2], s[j][3]));
        }
        mx0 = fmaxf(mx0, __shfl_xor_sync(0xffffffffu, mx0, 1));
        mx0 = fmaxf(mx0, __shfl_xor_sync(0xffffffffu, mx0, 2));
        mx1 = fmaxf(mx1, __shfl_xor_sync(0xffffffffu, mx1, 1));
        mx1 = fmaxf(mx1, __shfl_xor_sync(0xffffffffu, mx1, 2));

        const float mn0 = fmaxf(m0s, mx0), mn1 = fmaxf(m1s, mx1);
        const float al0 = __expf(m0s - mn0), al1 = __expf(m1s - mn1);
        m0s = mn0; m1s = mn1;

        float rs0 = 0.f, rs1 = 0.f;
#pragma unroll
        for (int j = 0; j < 8; ++j) {
            const float e0 = __expf(s[j][0] - mn0);
            const float e1 = __expf(s[j][1] - mn0);
            const float e2 = __expf(s[j][2] - mn1);
            const float e3 = __expf(s[j][3] - mn1);
            rs0 += e0 + e1; rs1 += e2 + e3;
            s[j][0] = to_tf32(e0); s[j][1] = to_tf32(e1);
            s[j][2] = to_tf32(e2); s[j][3] = to_tf32(e3);
        }
        rs0 += __shfl_xor_sync(0xffffffffu, rs0, 1);
        rs0 += __shfl_xor_sync(0xffffffffu, rs0, 2);
        rs1 += __shfl_xor_sync(0xffffffffu, rs1, 1);
        rs1 += __shfl_xor_sync(0xffffffffu, rs1, 2);
        l0s = l0s * al0 + rs0;
        l1s = l1s * al1 + rs1;
#pragma unroll
        for (int j = 0; j < 8; ++j) {
            o[j][0] *= al0; o[j][1] *= al0;
            o[j][2] *= al1; o[j][3] *= al1;
        }

#pragma unroll
        for (int s2 = 0; s2 < 8; ++s2) {
            const float v0 = __shfl_sync(0xffffffffu, s[s2][0], srcA);
            const float v1 = __shfl_sync(0xffffffffu, s[s2][1], srcA);
            const float v2 = __shfl_sync(0xffffffffu, s[s2][2], srcA);
            const float v3 = __shfl_sync(0xffffffffu, s[s2][3], srcA);
            const float w0 = __shfl_sync(0xffffffffu, s[s2][0], srcB);
            const float w1 = __shfl_sync(0xffffffffu, s[s2][1], srcB);
            const float w2 = __shfl_sync(0xffffffffu, s[s2][2], srcB);
            const float w3 = __shfl_sync(0xffffffffu, s[s2][3], srcB);
            const uint32_t a0 = F2U(odd ? v1 : v0);
            const uint32_t a1 = F2U(odd ? v3 : v2);
            const uint32_t a2 = F2U(odd ? w1 : w0);
            const uint32_t a3 = F2U(odd ? w3 : w2);
#pragma unroll
            for (int dt = 0; dt < 8; ++dt) {
                const uint32_t b0 = F2U(Vsb[(8 * s2 + t)     * 72 + 8 * dt + g]);
                const uint32_t b1 = F2U(Vsb[(8 * s2 + t + 4) * 72 + 8 * dt + g]);
                mma8(o[dt], a0, a1, a2, a3, b0, b1);
            }
        }

        if (cch + 1 < 32) {
            CP_WAIT0();
            __syncthreads();
        }
    }

    // ---- epilogue -> g_att [B,T,E], tf32-rounded (gemm_out stages it raw) ----
    const int b  = bh / HEADS;
    const int h  = bh % HEADS;
    const int t0 = q0 + 16 * w + g;
    const int t1 = t0 + 8;
    const float iv0 = 1.f / l0s, iv1 = 1.f / l1s;
    float* op0 = out + ((size_t)b * SEQ + t0) * EMBED + h * HDIM;
    float* op1 = out + ((size_t)b * SEQ + t1) * EMBED + h * HDIM;
#pragma unroll
    for (int j = 0; j < 8; ++j) {
        const int d = 8 * j + 2 * t;
        *(float2*)&op0[d] = make_float2(to_tf32(o[j][0] * iv0), to_tf32(o[j][1] * iv0));
        *(float2*)&op1[d] = make_float2(to_tf32(o[j][2] * iv1), to_tf32(o[j][3] * iv1));
    }
}

// ---------------------------------------------------------------------------
// kernel_launch
// inputs: 0 query, 1 key_in, 2 value, 3 Wq, 4 bq, 5 Wk, 6 bk, 7 Wv, 8 bv,
//         9 Wo, 10 bo
// ---------------------------------------------------------------------------
extern "C" void kernel_launch(void* const* d_in, const int* in_sizes, int n_in,
                              void* d_out, int out_size)
{
    (void)in_sizes; (void)n_in; (void)out_size;
    const float* query = (const float*)d_in[0];
    const float* key   = (const float*)d_in[1];
    const float* value = (const float*)d_in[2];
    const float* Wq = (const float*)d_in[3];
    const float* bq = (const float*)d_in[4];
    const float* Wk = (const float*)d_in[5];
    const float* bk = (const float*)d_in[6];
    const float* Wv = (const float*)d_in[7];
    const float* bv = (const float*)d_in[8];
    const float* Wo = (const float*)d_in[9];
    const float* bo = (const float*)d_in[10];
    float* out = (float*)d_out;

    float *qb, *kb, *vb, *ab;
    float *aq, *ak, *av, *wqp, *wkp, *wvp, *wop;
    cudaGetSymbolAddress((void**)&qb, g_q);
    cudaGetSymbolAddress((void**)&kb, g_k);
    cudaGetSymbolAddress((void**)&vb, g_v);
    cudaGetSymbolAddress((void**)&ab, g_att);
    cudaGetSymbolAddress((void**)&aq, g_aq);
    cudaGetSymbolAddress((void**)&ak, g_ak);
    cudaGetSymbolAddress((void**)&av, g_av);
    cudaGetSymbolAddress((void**)&wqp, g_wq);
    cudaGetSymbolAddress((void**)&wkp, g_wk);
    cudaGetSymbolAddress((void**)&wvp, g_wv);
    cudaGetSymbolAddress((void**)&wop, g_wo);

    const int GSMEM = (2 * 128 * 36 + 2 * 32 * 136) * 4;                      // 71680
    const int ASMEM = (128 * 68 + 2 * 64 * 68 + 2 * 64 * 72) * 4;             // 106496
    cudaFuncSetAttribute(gemm_qkv, cudaFuncAttributeMaxDynamicSharedMemorySize, GSMEM);
    cudaFuncSetAttribute(gemm_out, cudaFuncAttributeMaxDynamicSharedMemorySize, GSMEM);
    cudaFuncSetAttribute(attn_tc,  cudaFuncAttributeMaxDynamicSharedMemorySize, ASMEM);

    // 1. tf32 pre-round
    round_in<<<dim3(MROWS * EMBED / (256 * 4), 1, 3), 256>>>(query, key, value, aq, ak, av);
    round_w<<<dim3(EMBED * EMBED / (256 * 4), 1, 4), 256>>>(Wq, Wk, Wv, Wo, wqp, wkp, wvp, wop);

    // 2. fused QKV projection
    dim3 qkvgrid(EMBED / 128, MROWS / 128, 3);   // 6 x 32 x 3
    gemm_qkv<<<qkvgrid, 256, GSMEM>>>(bq, bk, bv, qb, kb, vb);

    // 3. attention
    dim3 agrid(SEQ / 128, BATCH * HEADS);        // 16 x 24
    attn_tc<<<agrid, 256, ASMEM>>>(qb, kb, vb, ab);

    // 4. output projection
    dim3 ogrid(EMBED / 128, MROWS / 128);        // 6 x 32
    gemm_out<<<ogrid, 256, GSMEM>>>(bo, out);
}

// round 17
// speedup vs baseline: 1.0287x; 1.0287x over previous
#include <cuda_runtime.h>
#include <cstdint>
#include <math.h>

#define EMBED 768
#define HEADS 12
#define HDIM  64
#define BATCH 2
#define SEQ   2048
#define MROWS (BATCH * SEQ)

// ---------------------------------------------------------------------------
// Scratch. g_q/g_k: [B,H,T,Dh] with d interleaved within 8-blocks
// (sigma: d=t -> 2t, d=t+4 -> 2t+1). g_v: [B,H,Dh,T] (transposed) with key
// interleaved within 8-blocks. Q pre-scaled by 0.125, all tf32-rounded.
// ---------------------------------------------------------------------------
__device__ float g_q[(size_t)BATCH * HEADS * SEQ * HDIM];
__device__ float g_k[(size_t)BATCH * HEADS * SEQ * HDIM];
__device__ float g_v[(size_t)BATCH * HEADS * SEQ * HDIM];
__device__ float g_att[(size_t)BATCH * SEQ * EMBED];        // [B,T,E]

__device__ __forceinline__ float to_tf32(float x) {
    float y; asm("cvt.rna.tf32.f32 %0, %1;" : "=f"(y) : "f"(x)); return y;
}
__device__ __forceinline__ uint32_t smem_u32(const void* p) {
    uint32_t a;
    asm("{ .reg .u64 t; cvta.to.shared.u64 t, %1; cvt.u32.u64 %0, t; }" : "=r"(a) : "l"(p));
    return a;
}

// m16n8k8 tf32 mma (hardware-verified R5/R10/R11/R13)
__device__ __forceinline__ void mma8(float (&c)[4],
                                     uint32_t a0, uint32_t a1, uint32_t a2, uint32_t a3,
                                     uint32_t b0, uint32_t b1) {
    asm volatile(
        "mma.sync.aligned.m16n8k8.row.col.f32.tf32.tf32.f32 "
        "{%0,%1,%2,%3}, {%4,%5,%6,%7}, {%8,%9}, {%0,%1,%2,%3};"
        : "+f"(c[0]), "+f"(c[1]), "+f"(c[2]), "+f"(c[3])
        : "r"(a0), "r"(a1), "r"(a2), "r"(a3), "r"(b0), "r"(b1));
}

#define F2U(x) __float_as_uint(x)

#define CP16(dst_u32, src_ptr) \
    asm volatile("cp.async.cg.shared.global [%0], [%1], 16;" \
                 :: "r"(dst_u32), "l"(__cvta_generic_to_global(src_ptr)) : "memory")
#define CP_COMMIT() asm volatile("cp.async.commit_group;" ::: "memory")
#define CP_WAIT0()  asm volatile("cp.async.wait_group 0;"  ::: "memory")

// ---------------------------------------------------------------------------
// GEMM v1 (R13-verified): CTA 128x128, 256 threads, 8 warps (4m x 2n),
// warp tile 32x64, K chunks of 32, double-buffered, register prefetch.
// ---------------------------------------------------------------------------
#define GEMM_PREAMBLE                                          \
    extern __shared__ float sm[];                              \
    float* As = sm;                                            \
    float* Bs = sm + 2 * 128 * 36;                             \
    const int tid  = threadIdx.x;                              \
    const int lane = tid & 31;                                 \
    const int g    = lane >> 2;                                \
    const int t    = lane & 3;                                 \
    const int wid  = tid >> 5;                                 \
    const int wm   = wid >> 1;                                 \
    const int wn   = wid & 1;                                  \
    const int m0   = blockIdx.y * 128;                         \
    const int n0   = blockIdx.x * 128;                         \
    const int ra = tid >> 1, ha = tid & 1;                     \
    const int kb = tid >> 3, nq = tid & 7;

#define GEMM_MAINLOOP(A, W)                                                      \
    float c[2][8][4];                                                            \
    _Pragma("unroll")                                                            \
    for (int ma = 0; ma < 2; ++ma)                                               \
        _Pragma("unroll")                                                        \
        for (int j = 0; j < 8; ++j)                                              \
            _Pragma("unroll")                                                    \
            for (int q = 0; q < 4; ++q) c[ma][j][q] = 0.f;                       \
    _Pragma("unroll")                                                            \
    for (int i = 0; i < 4; ++i) {                                                \
        float4 v = *(const float4*)&A[(size_t)(m0 + ra) * EMBED + ha * 16 + 4 * i]; \
        v.x = to_tf32(v.x); v.y = to_tf32(v.y); v.z = to_tf32(v.z); v.w = to_tf32(v.w); \
        *(float4*)&As[ra * 36 + ha * 16 + 4 * i] = v;                            \
    }                                                                            \
    _Pragma("unroll")                                                            \
    for (int i = 0; i < 4; ++i) {                                                \
        float4 v = *(const float4*)&W[(size_t)kb * EMBED + n0 + nq * 16 + 4 * i]; \
        v.x = to_tf32(v.x); v.y = to_tf32(v.y); v.z = to_tf32(v.z); v.w = to_tf32(v.w); \
        *(float4*)&Bs[kb * 136 + nq * 16 + 4 * i] = v;                           \
    }                                                                            \
    __syncthreads();                                                             \
    for (int ch = 0; ch < 24; ++ch) {                                            \
        const int buf = ch & 1;                                                  \
        float4 pa[4], pb[4];                                                     \
        if (ch + 1 < 24) {                                                       \
            const int k1 = (ch + 1) * 32;                                        \
            _Pragma("unroll")                                                    \
            for (int i = 0; i < 4; ++i)                                          \
                pa[i] = *(const float4*)&A[(size_t)(m0 + ra) * EMBED + k1 + ha * 16 + 4 * i]; \
            _Pragma("unroll")                                                    \
            for (int i = 0; i < 4; ++i)                                          \
                pb[i] = *(const float4*)&W[(size_t)(k1 + kb) * EMBED + n0 + nq * 16 + 4 * i]; \
        }                                                                        \
        const float* Ab = As + buf * 128 * 36;                                   \
        const float* Bb = Bs + buf * 32 * 136;                                   \
        _Pragma("unroll")                                                        \
        for (int s = 0; s < 4; ++s) {                                            \
            uint32_t a[2][4];                                                    \
            _Pragma("unroll")                                                    \
            for (int ma = 0; ma < 2; ++ma) {                                     \
                const int rb = wm * 32 + ma * 16;                                \
                a[ma][0] = F2U(Ab[(rb + g)     * 36 + 8 * s + t]);               \
                a[ma][1] = F2U(Ab[(rb + g + 8) * 36 + 8 * s + t]);               \
                a[ma][2] = F2U(Ab[(rb + g)     * 36 + 8 * s + t + 4]);           \
                a[ma][3] = F2U(Ab[(rb + g + 8) * 36 + 8 * s + t + 4]);           \
            }                                                                    \
            _Pragma("unroll")                                                    \
            for (int j = 0; j < 8; ++j) {                                        \
                const int col = wn * 64 + 8 * j + g;                             \
                const uint32_t b0 = F2U(Bb[(8 * s + t)     * 136 + col]);        \
                const uint32_t b1 = F2U(Bb[(8 * s + t + 4) * 136 + col]);        \
                mma8(c[0][j], a[0][0], a[0][1], a[0][2], a[0][3], b0, b1);       \
                mma8(c[1][j], a[1][0], a[1][1], a[1][2], a[1][3], b0, b1);       \
            }                                                                    \
        }                                                                        \
        if (ch + 1 < 24) {                                                       \
            float* Ab2 = As + ((ch + 1) & 1) * 128 * 36;                         \
            float* Bb2 = Bs + ((ch + 1) & 1) * 32 * 136;                         \
            _Pragma("unroll")                                                    \
            for (int i = 0; i < 4; ++i) {                                        \
                float4 v = pa[i];                                                \
                v.x = to_tf32(v.x); v.y = to_tf32(v.y); v.z = to_tf32(v.z); v.w = to_tf32(v.w); \
                *(float4*)&Ab2[ra * 36 + ha * 16 + 4 * i] = v;                   \
            }                                                                    \
            _Pragma("unroll")                                                    \
            for (int i = 0; i < 4; ++i) {                                        \
                float4 v = pb[i];                                                \
                v.x = to_tf32(v.x); v.y = to_tf32(v.y); v.z = to_tf32(v.z); v.w = to_tf32(v.w); \
                *(float4*)&Bb2[kb * 136 + nq * 16 + 4 * i] = v;                  \
            }                                                                    \
        }                                                                        \
        __syncthreads();                                                         \
    }

// ---------------------------------------------------------------------------
// Fused QKV projection. z=0/1 (Q/K): write [B,H,T,Dh] with d interleaved in
// 8-blocks. z=2 (V): write [B,H,Dh,T] transposed with key interleaved.
// tf32-rounded; Q pre-scaled by 0.125.
// ---------------------------------------------------------------------------
__global__ __launch_bounds__(256)
void gemm_qkv(const float* __restrict__ Aq, const float* __restrict__ Ak,
              const float* __restrict__ Avv,
              const float* __restrict__ Wq, const float* __restrict__ Wk,
              const float* __restrict__ Wv,
              const float* __restrict__ bq, const float* __restrict__ bk,
              const float* __restrict__ bv,
              float* __restrict__ Cq, float* __restrict__ Ck, float* __restrict__ Cv)
{
    GEMM_PREAMBLE
    const int z = blockIdx.z;
    const float* A    = (z == 0) ? Aq : (z == 1) ? Ak : Avv;
    const float* W    = (z == 0) ? Wq : (z == 1) ? Wk : Wv;
    const float* bias = (z == 0) ? bq : (z == 1) ? bk : bv;
    float*       C    = (z == 0) ? Cq : (z == 1) ? Ck : Cv;
    const float  scl  = (z == 0) ? 0.125f : 1.0f;

    GEMM_MAINLOOP(A, W)

    // sigma positions for the d-pair (2t, 2t+1) within an 8-block
    const int s0 = (t < 2) ? 4 * t : 4 * t - 7;
    const int s1 = (t < 2) ? 4 * t + 2 : 4 * t - 5;

#pragma unroll
    for (int ma = 0; ma < 2; ++ma) {
        const int r0 = m0 + wm * 32 + ma * 16 + g;
        const int r1 = r0 + 8;
#pragma unroll
        for (int j = 0; j < 8; ++j) {
            const int n = n0 + wn * 64 + 8 * j + 2 * t;
            const float bx = bias[n], by = bias[n + 1];
            const float v00 = to_tf32((c[ma][j][0] + bx) * scl);
            const float v01 = to_tf32((c[ma][j][1] + by) * scl);
            const float v10 = to_tf32((c[ma][j][2] + bx) * scl);
            const float v11 = to_tf32((c[ma][j][3] + by) * scl);
            const int h = n >> 6;
            const int d0 = n & 63;
            const int b0r = r0 >> 11, t0r = r0 & 2047;
            const int b1r = r1 >> 11, t1r = r1 & 2047;
            if (z < 2) {
                // [B,H,T,Dh], d interleaved: block base + sigma positions
                const int dbase = d0 & ~7;
                float* p0 = &C[(((size_t)b0r * HEADS + h) * SEQ + t0r) * HDIM + dbase];
                float* p1 = &C[(((size_t)b1r * HEADS + h) * SEQ + t1r) * HDIM + dbase];
                p0[s0] = v00; p0[s1] = v01;
                p1[s0] = v10; p1[s1] = v11;
            } else {
                // V^T: [B,H,Dh,T], key interleaved within 8-blocks.
                // key = t0r/t1r; key&7 = g -> sigma(g).
                const int sg = (g < 4) ? 2 * g : 2 * g - 7;
                const int k0 = (t0r & ~7) | sg;
                const int k1 = (t1r & ~7) | sg;
                float* pb0 = &C[(((size_t)b0r * HEADS + h) * HDIM + d0) * SEQ];
                float* pb1 = &C[(((size_t)b1r * HEADS + h) * HDIM + d0) * SEQ];
                pb0[k0] = v00; pb0[SEQ + k0] = v01;   // rows d0, d0+1
                pb1[k1] = v10; pb1[SEQ + k1] = v11;
            }
        }
    }
}

// ---------------------------------------------------------------------------
// Output projection: fp32 [M, E] (R13-verified)
// ---------------------------------------------------------------------------
__global__ __launch_bounds__(256)
void gemm_out(const float* __restrict__ A, const float* __restrict__ W,
              const float* __restrict__ bias, float* __restrict__ C)
{
    GEMM_PREAMBLE
    GEMM_MAINLOOP(A, W)

#pragma unroll
    for (int ma = 0; ma < 2; ++ma) {
        const int r0 = m0 + wm * 32 + ma * 16 + g;
        const int r1 = r0 + 8;
#pragma unroll
        for (int j = 0; j < 8; ++j) {
            const int n = n0 + wn * 64 + 8 * j + 2 * t;
            const float bx = bias[n], by = bias[n + 1];
            *(float2*)&C[(size_t)r0 * EMBED + n] = make_float2(c[ma][j][0] + bx, c[ma][j][1] + by);
            *(float2*)&C[(size_t)r1 * EMBED + n] = make_float2(c[ma][j][2] + bx, c[ma][j][3] + by);
        }
    }
}

// ---------------------------------------------------------------------------
// tf32 flash attention with paired (LDS.64) fragment loads.
// 256 threads, 8 warps, 16 q-rows/warp; 64-key cp.async double-buffered
// chunks; P in registers. All tiles row-stride 72 (== 8 mod 32): paired frag
// loads are bank-conflict-free. Q/K interleaved in d; V staged as V^T with
// interleaved keys (both baked into gmem by gemm_qkv).
// smem: Qs[128][72] | Ks[2][64][72] | Vt[2][64][72] = 110592 B -> 2 CTA/SM.
// ---------------------------------------------------------------------------
__global__ __launch_bounds__(256, 2)
void attn_tc(const float* __restrict__ Q, const float* __restrict__ K,
             const float* __restrict__ V, float* __restrict__ out)
{
    extern __shared__ float sm[];
    float* Qs  = sm;                      // 128*72
    float* Ks0 = Qs + 128 * 72;
    float* Ks1 = Ks0 + 64 * 72;
    float* Vt0 = Ks1 + 64 * 72;
    float* Vt1 = Vt0 + 64 * 72;

    const int tid  = threadIdx.x;
    const int lane = tid & 31;
    const int g    = lane >> 2;
    const int t    = lane & 3;
    const int w    = tid >> 5;
    const int bh   = blockIdx.y;
    const int q0   = blockIdx.x * 128;

    const float* Qp = Q + (size_t)bh * SEQ * HDIM;
    const float* Kp = K + (size_t)bh * SEQ * HDIM;
    const float* Vp = V + (size_t)bh * HDIM * SEQ;   // V^T layout

    // K staging: row kr = key, 16-float seg sk.  V staging: row vr = d.
    const int kr = tid >> 2, sk = tid & 3;
    const uint32_t kdst[2] = { smem_u32(Ks0 + kr * 72 + sk * 16),
                               smem_u32(Ks1 + kr * 72 + sk * 16) };
    const uint32_t vdst[2] = { smem_u32(Vt0 + kr * 72 + sk * 16),
                               smem_u32(Vt1 + kr * 72 + sk * 16) };
    const float* kcur = Kp + (size_t)kr * HDIM + sk * 16;   // advance by keys
    const float* vcur = Vp + (size_t)kr * SEQ + sk * 16;    // advance along T

    // ---- issue chunk 0, stage Q ----
    {
#pragma unroll
        for (int i = 0; i < 4; ++i) {
            CP16(kdst[0] + i * 16, kcur + 4 * i);
            CP16(vdst[0] + i * 16, vcur + 4 * i);
        }
        CP_COMMIT();
        const int rr = tid >> 1, sq = tid & 1;
        const float* qp = Qp + (size_t)(q0 + rr) * HDIM + sq * 32;
        float* qd = Qs + rr * 72 + sq * 32;
#pragma unroll
        for (int i = 0; i < 8; ++i)
            *(float4*)(qd + 4 * i) = *(const float4*)(qp + 4 * i);
    }
    CP_WAIT0();
    __syncthreads();

    float m0s = -INFINITY, m1s = -INFINITY, l0s = 0.f, l1s = 0.f;
    float o[8][4];
#pragma unroll
    for (int j = 0; j < 8; ++j)
#pragma unroll
        for (int q = 0; q < 4; ++q) o[j][q] = 0.f;

    const int srcA = 4 * g + (t >> 1);
    const int srcB = srcA + 2;
    const bool odd = (t & 1) != 0;

    for (int cch = 0; cch < 32; ++cch) {
        const int buf = cch & 1;
        if (cch + 1 < 32) {
            const float* kn = kcur + (size_t)(cch + 1) * 64 * HDIM;
            const float* vn = vcur + (size_t)(cch + 1) * 64;      // V^T: +64 keys
#pragma unroll
            for (int i = 0; i < 4; ++i) {
                CP16(kdst[buf ^ 1] + i * 16, kn + 4 * i);
                CP16(vdst[buf ^ 1] + i * 16, vn + 4 * i);
            }
            CP_COMMIT();
        }

        const float* Ksb = buf ? Ks1 : Ks0;
        const float* Vtb = buf ? Vt1 : Vt0;

        // ---- S = Q K^T over 64 keys (paired frag loads) ----
        float s[8][4];
#pragma unroll
        for (int j = 0; j < 8; ++j)
#pragma unroll
            for (int q = 0; q < 4; ++q) s[j][q] = 0.f;

#pragma unroll
        for (int ks = 0; ks < 8; ++ks) {
            const float* qr = Qs + (16 * w + g) * 72 + ks * 8 + 2 * t;
            const float2 qa = *(const float2*)qr;             // (k=t, k=t+4)
            const float2 qb = *(const float2*)(qr + 8 * 72);
            const uint32_t a0 = F2U(qa.x), a2 = F2U(qa.y);
            const uint32_t a1 = F2U(qb.x), a3 = F2U(qb.y);
#pragma unroll
            for (int j2 = 0; j2 < 8; ++j2) {
                const float2 kb2 = *(const float2*)(Ksb + (8 * j2 + g) * 72 + ks * 8 + 2 * t);
                mma8(s[j2], a0, a1, a2, a3, F2U(kb2.x), F2U(kb2.y));
            }
        }

        // ---- online softmax ----
        float mx0 = -INFINITY, mx1 = -INFINITY;
#pragma unroll
        for (int j = 0; j < 8; ++j) {
            mx0 = fmaxf(mx0, fmaxf(s[j][0], s[j][1]));
            mx1 = fmaxf(mx1, fmaxf(s[j][2], s[j][3]));
        }
        mx0 = fmaxf(mx0, __shfl_xor_sync(0xffffffffu, mx0, 1));
        mx0 = fmaxf(mx0, __shfl_xor_sync(0xffffffffu, mx0, 2));
        mx1 = fmaxf(mx1, __shfl_xor_sync(0xffffffffu, mx1, 1));
        mx1 = fmaxf(mx1, __shfl_xor_sync(0xffffffffu, mx1, 2));

        const float mn0 = fmaxf(m0s, mx0), mn1 = fmaxf(m1s, mx1);
        const float al0 = __expf(m0s - mn0), al1 = __expf(m1s - mn1);
        m0s = mn0; m1s = mn1;

        float rs0 = 0.f, rs1 = 0.f;
#pragma unroll
        for (int j = 0; j < 8; ++j) {
            const float e0 = __expf(s[j][0] - mn0);
            const float e1 = __expf(s[j][1] - mn0);
            const float e2 = __expf(s[j][2] - mn1);
            const float e3 = __expf(s[j][3] - mn1);
            rs0 += e0 + e1; rs1 += e2 + e3;
            s[j][0] = to_tf32(e0); s[j][1] = to_tf32(e1);
            s[j][2] = to_tf32(e2); s[j][3] = to_tf32(e3);
        }
        rs0 += __shfl_xor_sync(0xffffffffu, rs0, 1);
        rs0 += __shfl_xor_sync(0xffffffffu, rs0, 2);
        rs1 += __shfl_xor_sync(0xffffffffu, rs1, 1);
        rs1 += __shfl_xor_sync(0xffffffffu, rs1, 2);
        l0s = l0s * al0 + rs0;
        l1s = l1s * al1 + rs1;
#pragma unroll
        for (int j = 0; j < 8; ++j) {
            o[j][0] *= al0; o[j][1] *= al0;
            o[j][2] *= al1; o[j][3] *= al1;
        }

        // ---- O += P V (P via shuffle; V^T paired frag loads) ----
#pragma unroll
        for (int s2 = 0; s2 < 8; ++s2) {
            const float v0 = __shfl_sync(0xffffffffu, s[s2][0], srcA);
            const float v1 = __shfl_sync(0xffffffffu, s[s2][1], srcA);
            const float v2 = __shfl_sync(0xffffffffu, s[s2][2], srcA);
            const float v3 = __shfl_sync(0xffffffffu, s[s2][3], srcA);
            const float w0 = __shfl_sync(0xffffffffu, s[s2][0], srcB);
            const float w1 = __shfl_sync(0xffffffffu, s[s2][1], srcB);
            const float w2 = __shfl_sync(0xffffffffu, s[s2][2], srcB);
            const float w3 = __shfl_sync(0xffffffffu, s[s2][3], srcB);
            const uint32_t a0 = F2U(odd ? v1 : v0);
            const uint32_t a1 = F2U(odd ? v3 : v2);
            const uint32_t a2 = F2U(odd ? w1 : w0);
            const uint32_t a3 = F2U(odd ? w3 : w2);
#pragma unroll
            for (int dt = 0; dt < 8; ++dt) {
                const float2 vb2 = *(const float2*)(Vtb + (8 * dt + g) * 72 + s2 * 8 + 2 * t);
                mma8(o[dt], a0, a1, a2, a3, F2U(vb2.x), F2U(vb2.y));
            }
        }

        if (cch + 1 < 32) {
            CP_WAIT0();
            __syncthreads();
        }
    }

    // ---- epilogue: rows q0+16w+g and +8 -> g_att [B,T,E] fp32 ----
    const int b  = bh / HEADS;
    const int h  = bh % HEADS;
    const int t0 = q0 + 16 * w + g;
    const int t1 = t0 + 8;
    const float iv0 = 1.f / l0s, iv1 = 1.f / l1s;
    float* op0 = out + ((size_t)b * SEQ + t0) * EMBED + h * HDIM;
    float* op1 = out + ((size_t)b * SEQ + t1) * EMBED + h * HDIM;
#pragma unroll
    for (int j = 0; j < 8; ++j) {
        const int d = 8 * j + 2 * t;
        *(float2*)&op0[d] = make_float2(o[j][0] * iv0, o[j][1] * iv0);
        *(float2*)&op1[d] = make_float2(o[j][2] * iv1, o[j][3] * iv1);
    }
}

// ---------------------------------------------------------------------------
// kernel_launch
// inputs: 0 query, 1 key_in, 2 value, 3 Wq, 4 bq, 5 Wk, 6 bk, 7 Wv, 8 bv,
//         9 Wo, 10 bo
// ---------------------------------------------------------------------------
extern "C" void kernel_launch(void* const* d_in, const int* in_sizes, int n_in,
                              void* d_out, int out_size)
{
    (void)in_sizes; (void)n_in; (void)out_size;
    const float* query = (const float*)d_in[0];
    const float* key   = (const float*)d_in[1];
    const float* value = (const float*)d_in[2];
    const float* Wq = (const float*)d_in[3];
    const float* bq = (const float*)d_in[4];
    const float* Wk = (const float*)d_in[5];
    const float* bk = (const float*)d_in[6];
    const float* Wv = (const float*)d_in[7];
    const float* bv = (const float*)d_in[8];
    const float* Wo = (const float*)d_in[9];
    const float* bo = (const float*)d_in[10];
    float* out = (float*)d_out;

    float *qb, *kb, *vb, *ab;
    cudaGetSymbolAddress((void**)&qb, g_q);
    cudaGetSymbolAddress((void**)&kb, g_k);
    cudaGetSymbolAddress((void**)&vb, g_v);
    cudaGetSymbolAddress((void**)&ab, g_att);

    const int GSMEM = (2 * 128 * 36 + 2 * 32 * 136) * 4;          // 71680
    const int ASMEM = (128 * 72 + 2 * 64 * 72 + 2 * 64 * 72) * 4; // 110592
    cudaFuncSetAttribute(gemm_qkv, cudaFuncAttributeMaxDynamicSharedMemorySize, GSMEM);
    cudaFuncSetAttribute(gemm_out, cudaFuncAttributeMaxDynamicSharedMemorySize, GSMEM);
    cudaFuncSetAttribute(attn_tc,  cudaFuncAttributeMaxDynamicSharedMemorySize, ASMEM);

    dim3 qkvgrid(EMBED / 128, MROWS / 128, 3);   // 6 x 32 x 3
    gemm_qkv<<<qkvgrid, 256, GSMEM>>>(query, key, value, Wq, Wk, Wv,
                                      bq, bk, bv, qb, kb, vb);

    dim3 agrid(SEQ / 128, BATCH * HEADS);        // 16 x 24
    attn_tc<<<agrid, 256, ASMEM>>>(qb, kb, vb, ab);

    dim3 ogrid(EMBED / 128, MROWS / 128);        // 6 x 32
    gemm_out<<<ogrid, 256, GSMEM>>>(ab, Wo, bo, out);
}